// round 15
// baseline (speedup 1.0000x reference)
#include <cuda_runtime.h>
#include <cuda_bf16.h>
#include <cstddef>

// Fused YOLOv3 decode. Evidence over 14 rounds: all variants plateau at
// 4.0-4.6 TB/s regardless of LDG count/occupancy -> memory-pattern ceiling.
// R11 (full-warp 512B runs) had the best DRAM% (58.3); R12 (2 threads/quad)
// had the best time via thread count. R15 combines them: channels split
// across WARP PAIRS (even warp: classes 0-39, odd warp: classes 40-79, same
// 32 consecutive quads) -> every LDG.128 spans the full warp = 512B
// contiguous run, block covers 2KB adjacent. Merge via SMEM + 1 syncthreads
// (block-uniform branch; inactive threads clamp, never early-return).
//   blocks [0, quadBlocks)  : warp-pair split float4 path, scales 26 & 52
//   blocks [quadBlocks, ..) : scalar path, scale 13 (HW=169 not /4)

__device__ __forceinline__ float sigf(float x) { return 1.0f / (1.0f + __expf(-x)); }

__global__ __launch_bounds__(128, 8)
void yolo_decode_r15(const float* __restrict__ o13,
                     const float* __restrict__ o26,
                     const float* __restrict__ o52,
                     const float* __restrict__ a13,
                     const float* __restrict__ a26,
                     const float* __restrict__ a52,
                     const float* __restrict__ threshp,
                     const int*   __restrict__ casep,
                     float* __restrict__ boxes,   // [N,6]
                     float* __restrict__ mask,    // [N]
                     int B, int quadBlocks)
{
    const int C13 = B * 13 * 13;
    const int C26 = B * 26 * 26;
    const int C52 = B * 52 * 52;
    const int Q26 = C26 >> 2;
    const int Q52 = C52 >> 2;

    const int iv = __ldg(casep);
    const float case_f = (iv > 0 && iv < 1000000) ? (float)iv : __int_as_float(iv);
    const float inv_case = 1.0f / case_f;
    const float thresh = __ldg(threshp);

    if (blockIdx.x < quadBlocks) {
        // ------- warp-pair split float4 quad path: scales 26 & 52 -------
        // Block = 128 threads = 4 warps = 2 pairs. Pair g handles 32 quads.
        __shared__ float smx[64][4];   // odd-warp partial max   (per quad-in-block)
        __shared__ int   scl[64][4];   // odd-warp partial class

        const int nquad = 3 * (Q26 + Q52);
        const int wib   = threadIdx.x >> 5;            // warp in block 0..3
        const int lane  = threadIdx.x & 31;
        const int half  = wib & 1;                     // 0: classes 0-39, 1: 40-79
        const int pairb = wib >> 1;                    // pair in block 0..1
        const int gpair = blockIdx.x * 2 + pairb;      // global pair

        int qi = gpair * 32 + lane;                    // quad work-item
        const bool act = (qi < nquad);
        if (!act) qi = nquad - 1;                      // clamp (no early return!)

        const float* in; const float* anch;
        int S, HW, Qc, q, rowoff; float t;
        if (qi < 3 * Q26) { in = o26; anch = a26; S = 26; HW = 676;  Qc = Q26;
                            q = qi;           rowoff = C13 * 3;         t = 16.0f; }
        else              { in = o52; anch = a52; S = 52; HW = 2704; Qc = Q52;
                            q = qi - 3 * Q26; rowoff = (C13 + C26) * 3; t = 8.0f;  }
        const float scale = t * inv_case;

        const int a     = q / Qc;
        const int quadi = q - a * Qc;
        const int local = quadi << 2;
        const int b     = local / HW;
        const int pos   = local - b * HW;      // pos%4==0, pos+3 < HW

        const float* ptr = in + (size_t)(b * 255 + a * 85) * HW + pos;  // 16B aligned

        // ---- phase 1: box channels (even warps only), written early ----
        if (half == 0 && act) {
            const float4 q0 = *(const float4*)(ptr);
            const float4 q1 = *(const float4*)(ptr + HW);
            const float4 q2 = *(const float4*)(ptr + 2 * HW);
            const float4 q3 = *(const float4*)(ptr + 3 * HW);
            const float4 q4 = *(const float4*)(ptr + 4 * HW);

            const float ax = __ldg(anch + a * 2 + 0);
            const float ay = __ldg(anch + a * 2 + 1);
            const int h0 = pos / S;
            const int w0 = pos - h0 * S;

            const float oo[4] = {q0.x, q0.y, q0.z, q0.w};
            const float ox[4] = {q1.x, q1.y, q1.z, q1.w};
            const float oy[4] = {q2.x, q2.y, q2.z, q2.w};
            const float ow[4] = {q3.x, q3.y, q3.z, q3.w};
            const float oh[4] = {q4.x, q4.y, q4.z, q4.w};

            #pragma unroll
            for (int i = 0; i < 4; ++i) {
                int wi = w0 + i, hi = h0;
                if (wi >= S) { wi -= S; hi += 1; }   // at most one wrap (4 <= S)
                const int row = rowoff + (local + i) * 3 + a;
                float* r = boxes + (size_t)row * 6;
                *(float2*)(r)     = make_float2(sigf(oo[i]), ((float)wi + ox[i]) * scale);
                *(float2*)(r + 2) = make_float2(((float)hi + oy[i]) * scale,
                                                ax * __expf(ow[i]) * inv_case);
                r[4] = ay * __expf(oh[i]) * inv_case;
                mask[row] = (oo[i] > thresh) ? 1.0f : 0.0f;
            }
        }

        // ---- phase 2: argmax over this warp's 40 class channels ----
        // Full warp on 32 consecutive quads -> 512B contiguous per LDG.128.
        // MLP=10 float4 batches; unroll-1 outer loop (no front-batch spill).
        // Strict '>' keeps FIRST max within the 40-channel half.
        float mx[4] = {-3.4e38f, -3.4e38f, -3.4e38f, -3.4e38f};
        int   cl[4] = {0, 0, 0, 0};
        const int dbase = half * 40;
        const float* pc = ptr + (5 + dbase) * HW;
        #pragma unroll 1
        for (int d0 = 0; d0 < 40; d0 += 10) {
            float4 v[10];
            #pragma unroll
            for (int i = 0; i < 10; ++i)
                v[i] = *(const float4*)(pc + (d0 + i) * HW);
            #pragma unroll
            for (int i = 0; i < 10; ++i) {
                const int d = dbase + d0 + i;
                if (v[i].x > mx[0]) { mx[0] = v[i].x; cl[0] = d; }
                if (v[i].y > mx[1]) { mx[1] = v[i].y; cl[1] = d; }
                if (v[i].z > mx[2]) { mx[2] = v[i].z; cl[2] = d; }
                if (v[i].w > mx[3]) { mx[3] = v[i].w; cl[3] = d; }
            }
        }

        // ---- phase 3: merge pair halves via SMEM ----
        const int slot = pairb * 32 + lane;            // 0..63
        if (half == 1) {
            #pragma unroll
            for (int i = 0; i < 4; ++i) { smx[slot][i] = mx[i]; scl[slot][i] = cl[i]; }
        }
        __syncthreads();
        if (half == 0 && act) {
            #pragma unroll
            for (int i = 0; i < 4; ++i) {
                const float mo = smx[slot][i];
                // even warp holds classes 0-39 (earlier indices): odd half wins
                // only on strictly greater -> first-max tie rule preserved.
                const int c = (mo > mx[i]) ? scl[slot][i] : cl[i];
                const int row = rowoff + (local + i) * 3 + a;
                boxes[(size_t)row * 6 + 5] = (float)c;
            }
        }
    } else {
        // ---------------- scalar path: scale 13 ----------------
        const int idx = (blockIdx.x - quadBlocks) * blockDim.x + threadIdx.x;
        if (idx >= 3 * C13) return;

        const int a     = idx / C13;
        const int local = idx - a * C13;
        const int HW = 169, S = 13;
        const int b   = local / HW;
        const int pos = local - b * HW;
        const int h   = pos / S;
        const int w   = pos - h * S;
        const float scale = 32.0f * inv_case;

        const float* ptr = o13 + (size_t)(b * 255 + a * 85) * HW + pos;
        const int row = local * 3 + a;
        float* r = boxes + (size_t)row * 6;

        {
            const float v0 = __ldg(ptr);
            const float v1 = __ldg(ptr + HW);
            const float v2 = __ldg(ptr + 2 * HW);
            const float v3 = __ldg(ptr + 3 * HW);
            const float v4 = __ldg(ptr + 4 * HW);
            *(float2*)(r)     = make_float2(sigf(v0), ((float)w + v1) * scale);
            *(float2*)(r + 2) = make_float2(((float)h + v2) * scale,
                                            __ldg(a13 + a * 2 + 0) * __expf(v3) * inv_case);
            r[4] = __ldg(a13 + a * 2 + 1) * __expf(v4) * inv_case;
            mask[row] = (v0 > thresh) ? 1.0f : 0.0f;
        }

        float maxv = -3.4e38f; int cls = 0;
        const float* pc = ptr + 5 * HW;
        #pragma unroll 1
        for (int d0 = 0; d0 < 80; d0 += 10) {
            float v[10];
            #pragma unroll
            for (int i = 0; i < 10; ++i) v[i] = __ldg(pc + (d0 + i) * HW);
            #pragma unroll
            for (int i = 0; i < 10; ++i)
                if (v[i] > maxv) { maxv = v[i]; cls = d0 + i; }
        }
        r[5] = (float)cls;
    }
}

extern "C" void kernel_launch(void* const* d_in, const int* in_sizes, int n_in,
                              void* d_out, int out_size)
{
    const float* o13 = (const float*)d_in[0];
    const float* o26 = (const float*)d_in[1];
    const float* o52 = (const float*)d_in[2];
    const float* a13 = (const float*)d_in[3];
    const float* a26 = (const float*)d_in[4];
    const float* a52 = (const float*)d_in[5];
    const float* th  = (const float*)d_in[6];
    const int*   cs  = (const int*)  d_in[7];

    const int B = in_sizes[0] / (255 * 13 * 13);

    const int C13 = B * 13 * 13;
    const int C26 = B * 26 * 26;
    const int C52 = B * 52 * 52;
    const int N = (C13 + C26 + C52) * 3;

    float* boxes = (float*)d_out;                   // [N,6]
    float* mask  = (float*)d_out + (size_t)N * 6;   // [N]

    const int TPB = 128;
    const int nquad = 3 * ((C26 >> 2) + (C52 >> 2));
    const int pairs      = (nquad + 31) / 32;        // 32 quads per warp pair
    const int quadBlocks = (pairs + 1) / 2;          // 2 pairs per 128-thr block
    const int s13Blocks  = (3 * C13 + TPB - 1) / TPB;

    yolo_decode_r15<<<quadBlocks + s13Blocks, TPB>>>(
        o13, o26, o52, a13, a26, a52, th, cs, boxes, mask, B, quadBlocks);
}

// round 16
// speedup vs baseline: 1.0760x; 1.0760x over previous
#include <cuda_runtime.h>
#include <cuda_bf16.h>
#include <cstddef>

// Fused YOLOv3 decode — R12 structure (best: 27.4us) + streaming cache hints.
// 15 rounds of evidence: every structural variant (scalar/float2/float4,
// occupancy 22-63%, warp-split, SMEM merge, persistent grid, pipelining)
// equilibrates at 4.0-4.6 TB/s -> pattern-limited. R12 sits on that ceiling.
// This round keeps R12 byte-for-byte and only switches the (zero-reuse,
// pure-streaming) loads to __ldcs and stores to __stcs: evict-first policy,
// no L1 allocation, less L2 churn for the 116MB once-read stream.
//   blocks [0, quadBlocks)  : split-channel float4 path, scales 26 & 52
//                             (2 threads/quad; lanes 0-15 classes 0-39,
//                              lanes 16-31 classes 40-79, shfl_xor(16) merge)
//   blocks [quadBlocks, ..) : scalar path, scale 13 (HW=169 not /4)

__device__ __forceinline__ float sigf(float x) { return 1.0f / (1.0f + __expf(-x)); }

__global__ __launch_bounds__(128, 8)
void yolo_decode_r16(const float* __restrict__ o13,
                     const float* __restrict__ o26,
                     const float* __restrict__ o52,
                     const float* __restrict__ a13,
                     const float* __restrict__ a26,
                     const float* __restrict__ a52,
                     const float* __restrict__ threshp,
                     const int*   __restrict__ casep,
                     float* __restrict__ boxes,   // [N,6]
                     float* __restrict__ mask,    // [N]
                     int B, int quadBlocks)
{
    const int C13 = B * 13 * 13;
    const int C26 = B * 26 * 26;
    const int C52 = B * 52 * 52;
    const int Q26 = C26 >> 2;
    const int Q52 = C52 >> 2;

    const int iv = __ldg(casep);
    const float case_f = (iv > 0 && iv < 1000000) ? (float)iv : __int_as_float(iv);
    const float inv_case = 1.0f / case_f;
    const float thresh = __ldg(threshp);

    if (blockIdx.x < quadBlocks) {
        // ------- split-channel float4 quad path: scales 26 & 52 -------
        const int nquad = 3 * (Q26 + Q52);
        const int gw   = (blockIdx.x * blockDim.x + threadIdx.x) >> 5;  // global warp
        const int lane = threadIdx.x & 31;
        const int hh   = lane >> 4;          // channel half: 0 -> 0..39, 1 -> 40..79
        const int ql   = lane & 15;          // quad-within-warp

        int qi = gw * 16 + ql;               // quad work-item
        const bool act = (qi < nquad);
        if (!act) qi = nquad - 1;            // clamp keeps lane pair (l, l^16) coherent

        const float* in; const float* anch;
        int S, HW, Qc, q, rowoff; float t;
        if (qi < 3 * Q26) { in = o26; anch = a26; S = 26; HW = 676;  Qc = Q26;
                            q = qi;           rowoff = C13 * 3;         t = 16.0f; }
        else              { in = o52; anch = a52; S = 52; HW = 2704; Qc = Q52;
                            q = qi - 3 * Q26; rowoff = (C13 + C26) * 3; t = 8.0f;  }
        const float scale = t * inv_case;

        const int a     = q / Qc;
        const int quadi = q - a * Qc;
        const int local = quadi << 2;
        const int b     = local / HW;
        const int pos   = local - b * HW;      // pos%4==0, pos+3 < HW

        const float* ptr = in + (size_t)(b * 255 + a * 85) * HW + pos;  // 16B aligned

        // ---- phase 1: box channels (low half-warp only), written early ----
        if (hh == 0 && act) {
            const float4 q0 = __ldcs((const float4*)(ptr));
            const float4 q1 = __ldcs((const float4*)(ptr + HW));
            const float4 q2 = __ldcs((const float4*)(ptr + 2 * HW));
            const float4 q3 = __ldcs((const float4*)(ptr + 3 * HW));
            const float4 q4 = __ldcs((const float4*)(ptr + 4 * HW));

            const float ax = __ldg(anch + a * 2 + 0);
            const float ay = __ldg(anch + a * 2 + 1);
            const int h0 = pos / S;
            const int w0 = pos - h0 * S;

            const float oo[4] = {q0.x, q0.y, q0.z, q0.w};
            const float ox[4] = {q1.x, q1.y, q1.z, q1.w};
            const float oy[4] = {q2.x, q2.y, q2.z, q2.w};
            const float ow[4] = {q3.x, q3.y, q3.z, q3.w};
            const float oh[4] = {q4.x, q4.y, q4.z, q4.w};

            #pragma unroll
            for (int i = 0; i < 4; ++i) {
                int wi = w0 + i, hi = h0;
                if (wi >= S) { wi -= S; hi += 1; }   // at most one wrap (4 <= S)
                const int row = rowoff + (local + i) * 3 + a;
                float* r = boxes + (size_t)row * 6;
                __stcs((float2*)(r),
                       make_float2(sigf(oo[i]), ((float)wi + ox[i]) * scale));
                __stcs((float2*)(r + 2),
                       make_float2(((float)hi + oy[i]) * scale,
                                   ax * __expf(ow[i]) * inv_case));
                __stcs(r + 4, ay * __expf(oh[i]) * inv_case);
                __stcs(&mask[row], (oo[i] > thresh) ? 1.0f : 0.0f);
            }
        }

        // ---- phase 2: argmax over this thread's 40 class channels ----
        // MLP=10 float4 streaming loads; unroll-1 outer loop (no front-batch
        // inflation -> no spill). Strict '>' keeps FIRST max within the half.
        float mx[4] = {-3.4e38f, -3.4e38f, -3.4e38f, -3.4e38f};
        int   cl[4] = {0, 0, 0, 0};
        const float* pc = ptr + (5 + hh * 40) * HW;
        const int dbase = hh * 40;
        #pragma unroll 1
        for (int d0 = 0; d0 < 40; d0 += 10) {
            float4 v[10];
            #pragma unroll
            for (int i = 0; i < 10; ++i)
                v[i] = __ldcs((const float4*)(pc + (d0 + i) * HW));
            #pragma unroll
            for (int i = 0; i < 10; ++i) {
                const int d = dbase + d0 + i;
                if (v[i].x > mx[0]) { mx[0] = v[i].x; cl[0] = d; }
                if (v[i].y > mx[1]) { mx[1] = v[i].y; cl[1] = d; }
                if (v[i].z > mx[2]) { mx[2] = v[i].z; cl[2] = d; }
                if (v[i].w > mx[3]) { mx[3] = v[i].w; cl[3] = d; }
            }
        }

        // ---- phase 3: merge halves (lanes l <-> l^16), low half writes ----
        #pragma unroll
        for (int i = 0; i < 4; ++i) {
            const float mo = __shfl_xor_sync(0xffffffffu, mx[i], 16);
            const int   co = __shfl_xor_sync(0xffffffffu, cl[i], 16);
            // low half holds earlier class indices: high wins only on strictly
            // greater -> first-max tie rule preserved.
            if (mo > mx[i]) { mx[i] = mo; cl[i] = co; }
        }
        if (hh == 0 && act) {
            #pragma unroll
            for (int i = 0; i < 4; ++i) {
                const int row = rowoff + (local + i) * 3 + a;
                __stcs(&boxes[(size_t)row * 6 + 5], (float)cl[i]);
            }
        }
    } else {
        // ---------------- scalar path: scale 13 ----------------
        const int idx = (blockIdx.x - quadBlocks) * blockDim.x + threadIdx.x;
        if (idx >= 3 * C13) return;

        const int a     = idx / C13;
        const int local = idx - a * C13;
        const int HW = 169, S = 13;
        const int b   = local / HW;
        const int pos = local - b * HW;
        const int h   = pos / S;
        const int w   = pos - h * S;
        const float scale = 32.0f * inv_case;

        const float* ptr = o13 + (size_t)(b * 255 + a * 85) * HW + pos;
        const int row = local * 3 + a;
        float* r = boxes + (size_t)row * 6;

        {
            const float v0 = __ldcs(ptr);
            const float v1 = __ldcs(ptr + HW);
            const float v2 = __ldcs(ptr + 2 * HW);
            const float v3 = __ldcs(ptr + 3 * HW);
            const float v4 = __ldcs(ptr + 4 * HW);
            __stcs((float2*)(r), make_float2(sigf(v0), ((float)w + v1) * scale));
            __stcs((float2*)(r + 2),
                   make_float2(((float)h + v2) * scale,
                               __ldg(a13 + a * 2 + 0) * __expf(v3) * inv_case));
            __stcs(r + 4, __ldg(a13 + a * 2 + 1) * __expf(v4) * inv_case);
            __stcs(&mask[row], (v0 > thresh) ? 1.0f : 0.0f);
        }

        float maxv = -3.4e38f; int cls = 0;
        const float* pc = ptr + 5 * HW;
        #pragma unroll 1
        for (int d0 = 0; d0 < 80; d0 += 16) {
            float v[16];
            #pragma unroll
            for (int i = 0; i < 16; ++i) v[i] = __ldcs(pc + (d0 + i) * HW);
            #pragma unroll
            for (int i = 0; i < 16; ++i)
                if (v[i] > maxv) { maxv = v[i]; cls = d0 + i; }
        }
        __stcs(r + 5, (float)cls);
    }
}

extern "C" void kernel_launch(void* const* d_in, const int* in_sizes, int n_in,
                              void* d_out, int out_size)
{
    const float* o13 = (const float*)d_in[0];
    const float* o26 = (const float*)d_in[1];
    const float* o52 = (const float*)d_in[2];
    const float* a13 = (const float*)d_in[3];
    const float* a26 = (const float*)d_in[4];
    const float* a52 = (const float*)d_in[5];
    const float* th  = (const float*)d_in[6];
    const int*   cs  = (const int*)  d_in[7];

    const int B = in_sizes[0] / (255 * 13 * 13);

    const int C13 = B * 13 * 13;
    const int C26 = B * 26 * 26;
    const int C52 = B * 52 * 52;
    const int N = (C13 + C26 + C52) * 3;

    float* boxes = (float*)d_out;                   // [N,6]
    float* mask  = (float*)d_out + (size_t)N * 6;   // [N]

    const int TPB = 128;
    const int nquad = 3 * ((C26 >> 2) + (C52 >> 2));
    const int quadWarps   = (nquad + 15) / 16;       // 16 quads per warp, 2 threads/quad
    const int quadThreads = quadWarps * 32;
    const int quadBlocks  = (quadThreads + TPB - 1) / TPB;
    const int s13Blocks   = (3 * C13 + TPB - 1) / TPB;

    yolo_decode_r16<<<quadBlocks + s13Blocks, TPB>>>(
        o13, o26, o52, a13, a26, a52, th, cs, boxes, mask, B, quadBlocks);
}

// round 17
// speedup vs baseline: 1.0862x; 1.0094x over previous
#include <cuda_runtime.h>
#include <cuda_bf16.h>
#include <cstddef>

// Fused YOLOv3 decode — R16 structure + SINGLE-WAVE grid.
// R16: 1395 blocks @ 8/SM = 1.18 waves -> ~18% of wall time runs a near-empty
// chip. R17: each quad-path thread handles TWO quad warp-chunks (gw and
// gw+halfWarps; lane adjacency preserved per iteration), halving quad blocks:
// total grid 761 < 1184 capacity = exactly one wave. #pragma unroll 1 on the
// 2-iteration loop keeps the register frame identical to R16 (no interleave).
//   blocks [0, quadBlocks)  : split-channel float4 path, scales 26 & 52
//                             (2 threads/quad; lanes 0-15 classes 0-39,
//                              lanes 16-31 classes 40-79, shfl_xor(16) merge)
//   blocks [quadBlocks, ..) : scalar path, scale 13 (HW=169 not /4)

__device__ __forceinline__ float sigf(float x) { return 1.0f / (1.0f + __expf(-x)); }

__global__ __launch_bounds__(128, 8)
void yolo_decode_r17(const float* __restrict__ o13,
                     const float* __restrict__ o26,
                     const float* __restrict__ o52,
                     const float* __restrict__ a13,
                     const float* __restrict__ a26,
                     const float* __restrict__ a52,
                     const float* __restrict__ threshp,
                     const int*   __restrict__ casep,
                     float* __restrict__ boxes,   // [N,6]
                     float* __restrict__ mask,    // [N]
                     int B, int quadBlocks, int halfWarps)
{
    const int C13 = B * 13 * 13;
    const int C26 = B * 26 * 26;
    const int C52 = B * 52 * 52;
    const int Q26 = C26 >> 2;
    const int Q52 = C52 >> 2;

    const int iv = __ldg(casep);
    const float case_f = (iv > 0 && iv < 1000000) ? (float)iv : __int_as_float(iv);
    const float inv_case = 1.0f / case_f;
    const float thresh = __ldg(threshp);

    if (blockIdx.x < quadBlocks) {
        // ------- split-channel float4 quad path: scales 26 & 52 -------
        const int nquad = 3 * (Q26 + Q52);
        const int gw0  = (blockIdx.x * blockDim.x + threadIdx.x) >> 5;  // base warp-chunk
        const int lane = threadIdx.x & 31;
        const int hh   = lane >> 4;          // channel half: 0 -> 0..39, 1 -> 40..79
        const int ql   = lane & 15;          // quad-within-chunk

        #pragma unroll 1
        for (int it = 0; it < 2; ++it) {
            const int gw = gw0 + it * halfWarps;

            int qi = gw * 16 + ql;               // quad work-item
            const bool act = (qi < nquad);
            if (!act) qi = nquad - 1;            // clamp keeps lane pair coherent

            const float* in; const float* anch;
            int S, HW, Qc, q, rowoff; float t;
            if (qi < 3 * Q26) { in = o26; anch = a26; S = 26; HW = 676;  Qc = Q26;
                                q = qi;           rowoff = C13 * 3;         t = 16.0f; }
            else              { in = o52; anch = a52; S = 52; HW = 2704; Qc = Q52;
                                q = qi - 3 * Q26; rowoff = (C13 + C26) * 3; t = 8.0f;  }
            const float scale = t * inv_case;

            const int a     = q / Qc;
            const int quadi = q - a * Qc;
            const int local = quadi << 2;
            const int b     = local / HW;
            const int pos   = local - b * HW;      // pos%4==0, pos+3 < HW

            const float* ptr = in + (size_t)(b * 255 + a * 85) * HW + pos;  // 16B aligned

            // ---- phase 1: box channels (low half-warp only), written early ----
            if (hh == 0 && act) {
                const float4 q0 = __ldcs((const float4*)(ptr));
                const float4 q1 = __ldcs((const float4*)(ptr + HW));
                const float4 q2 = __ldcs((const float4*)(ptr + 2 * HW));
                const float4 q3 = __ldcs((const float4*)(ptr + 3 * HW));
                const float4 q4 = __ldcs((const float4*)(ptr + 4 * HW));

                const float ax = __ldg(anch + a * 2 + 0);
                const float ay = __ldg(anch + a * 2 + 1);
                const int h0 = pos / S;
                const int w0 = pos - h0 * S;

                const float oo[4] = {q0.x, q0.y, q0.z, q0.w};
                const float ox[4] = {q1.x, q1.y, q1.z, q1.w};
                const float oy[4] = {q2.x, q2.y, q2.z, q2.w};
                const float ow[4] = {q3.x, q3.y, q3.z, q3.w};
                const float oh[4] = {q4.x, q4.y, q4.z, q4.w};

                #pragma unroll
                for (int i = 0; i < 4; ++i) {
                    int wi = w0 + i, hi = h0;
                    if (wi >= S) { wi -= S; hi += 1; }   // at most one wrap (4 <= S)
                    const int row = rowoff + (local + i) * 3 + a;
                    float* r = boxes + (size_t)row * 6;
                    __stcs((float2*)(r),
                           make_float2(sigf(oo[i]), ((float)wi + ox[i]) * scale));
                    __stcs((float2*)(r + 2),
                           make_float2(((float)hi + oy[i]) * scale,
                                       ax * __expf(ow[i]) * inv_case));
                    __stcs(r + 4, ay * __expf(oh[i]) * inv_case);
                    __stcs(&mask[row], (oo[i] > thresh) ? 1.0f : 0.0f);
                }
            }

            // ---- phase 2: argmax over this thread's 40 class channels ----
            float mx[4] = {-3.4e38f, -3.4e38f, -3.4e38f, -3.4e38f};
            int   cl[4] = {0, 0, 0, 0};
            const float* pc = ptr + (5 + hh * 40) * HW;
            const int dbase = hh * 40;
            #pragma unroll 1
            for (int d0 = 0; d0 < 40; d0 += 10) {
                float4 v[10];
                #pragma unroll
                for (int i = 0; i < 10; ++i)
                    v[i] = __ldcs((const float4*)(pc + (d0 + i) * HW));
                #pragma unroll
                for (int i = 0; i < 10; ++i) {
                    const int d = dbase + d0 + i;
                    if (v[i].x > mx[0]) { mx[0] = v[i].x; cl[0] = d; }
                    if (v[i].y > mx[1]) { mx[1] = v[i].y; cl[1] = d; }
                    if (v[i].z > mx[2]) { mx[2] = v[i].z; cl[2] = d; }
                    if (v[i].w > mx[3]) { mx[3] = v[i].w; cl[3] = d; }
                }
            }

            // ---- phase 3: merge halves (lanes l <-> l^16), low half writes ----
            #pragma unroll
            for (int i = 0; i < 4; ++i) {
                const float mo = __shfl_xor_sync(0xffffffffu, mx[i], 16);
                const int   co = __shfl_xor_sync(0xffffffffu, cl[i], 16);
                // low half holds earlier class indices: high wins only on
                // strictly greater -> first-max tie rule preserved.
                if (mo > mx[i]) { mx[i] = mo; cl[i] = co; }
            }
            if (hh == 0 && act) {
                #pragma unroll
                for (int i = 0; i < 4; ++i) {
                    const int row = rowoff + (local + i) * 3 + a;
                    __stcs(&boxes[(size_t)row * 6 + 5], (float)cl[i]);
                }
            }
        }
    } else {
        // ---------------- scalar path: scale 13 ----------------
        const int idx = (blockIdx.x - quadBlocks) * blockDim.x + threadIdx.x;
        if (idx >= 3 * C13) return;

        const int a     = idx / C13;
        const int local = idx - a * C13;
        const int HW = 169, S = 13;
        const int b   = local / HW;
        const int pos = local - b * HW;
        const int h   = pos / S;
        const int w   = pos - h * S;
        const float scale = 32.0f * inv_case;

        const float* ptr = o13 + (size_t)(b * 255 + a * 85) * HW + pos;
        const int row = local * 3 + a;
        float* r = boxes + (size_t)row * 6;

        {
            const float v0 = __ldcs(ptr);
            const float v1 = __ldcs(ptr + HW);
            const float v2 = __ldcs(ptr + 2 * HW);
            const float v3 = __ldcs(ptr + 3 * HW);
            const float v4 = __ldcs(ptr + 4 * HW);
            __stcs((float2*)(r), make_float2(sigf(v0), ((float)w + v1) * scale));
            __stcs((float2*)(r + 2),
                   make_float2(((float)h + v2) * scale,
                               __ldg(a13 + a * 2 + 0) * __expf(v3) * inv_case));
            __stcs(r + 4, __ldg(a13 + a * 2 + 1) * __expf(v4) * inv_case);
            __stcs(&mask[row], (v0 > thresh) ? 1.0f : 0.0f);
        }

        float maxv = -3.4e38f; int cls = 0;
        const float* pc = ptr + 5 * HW;
        #pragma unroll 1
        for (int d0 = 0; d0 < 80; d0 += 16) {
            float v[16];
            #pragma unroll
            for (int i = 0; i < 16; ++i) v[i] = __ldcs(pc + (d0 + i) * HW);
            #pragma unroll
            for (int i = 0; i < 16; ++i)
                if (v[i] > maxv) { maxv = v[i]; cls = d0 + i; }
        }
        __stcs(r + 5, (float)cls);
    }
}

extern "C" void kernel_launch(void* const* d_in, const int* in_sizes, int n_in,
                              void* d_out, int out_size)
{
    const float* o13 = (const float*)d_in[0];
    const float* o26 = (const float*)d_in[1];
    const float* o52 = (const float*)d_in[2];
    const float* a13 = (const float*)d_in[3];
    const float* a26 = (const float*)d_in[4];
    const float* a52 = (const float*)d_in[5];
    const float* th  = (const float*)d_in[6];
    const int*   cs  = (const int*)  d_in[7];

    const int B = in_sizes[0] / (255 * 13 * 13);

    const int C13 = B * 13 * 13;
    const int C26 = B * 26 * 26;
    const int C52 = B * 52 * 52;
    const int N = (C13 + C26 + C52) * 3;

    float* boxes = (float*)d_out;                   // [N,6]
    float* mask  = (float*)d_out + (size_t)N * 6;   // [N]

    const int TPB = 128;
    const int nquad = 3 * ((C26 >> 2) + (C52 >> 2));
    const int quadWarps = (nquad + 15) / 16;         // 16 quads per warp-chunk
    const int halfWarps = (quadWarps + 1) / 2;       // each warp does 2 chunks
    const int quadBlocks = (halfWarps * 32 + TPB - 1) / TPB;
    const int s13Blocks  = (3 * C13 + TPB - 1) / TPB;

    yolo_decode_r17<<<quadBlocks + s13Blocks, TPB>>>(
        o13, o26, o52, a13, a26, a52, th, cs, boxes, mask, B, quadBlocks, halfWarps);
}